// round 17
// baseline (speedup 1.0000x reference)
// FSAS_V5 fused forward — one CTA per 8x8 patch, 512 threads.
// R17 = R15 (best: 596us) + f32x2-vectorized phase 3 (RoPE, pixel pairs) and
// phase 6 (corr->bf16 tiles, kp pairs). Persistent-CTA experiment reverted.
#include <cuda_runtime.h>
#include <cuda_bf16.h>
#include <cstdint>

#define HH 256
#define WW 256
#define EPSF 1e-6f
#define L2T_OVER_32 0.41524101186092030f

// ---- dynamic smem layout (float offsets) ----
#define OFF_QKV  0                 // 384 * 65 fp32
#define OFF_HID  24960             // 128 * 101 fp32 hidden chunk
#define OFF_CORR OFF_HID           // 128 * 65 overlay (phase 4+)
#define OFF_G    37888             // g_norm[128], g_qnorm[128], g_knorm[128]
#define OFF_SC   38272             // sincos: cos[512], sin[512]
#define OFF_RQ   40448
#define OFF_RK   40512
#define OFF_RN   40576
#define ARENA_F  40640             // bf16 tile arena
#define XHI 0
#define XLO 14976
#define DWB 29952                  // dw weight double buffer (2 x 4608 B)
#define CBH 34816
#define CBL 52224
#define ARENA_BYTES 69632
#define SMEM_BYTES (ARENA_F * 4 + ARENA_BYTES)   // 232,192 B

// ---- prepacked weight FRAGMENTS (constant across CTAs) ----
__device__ uint32_t g_wfh[3][4096];
__device__ uint32_t g_wfl[3][4096];
__device__ uint32_t g_pfh[4096];
__device__ uint32_t g_pfl[4096];

__device__ __forceinline__ uint32_t smem_u32(const void* p) {
    uint32_t a;
    asm("{ .reg .u64 t; cvta.to.shared.u64 t, %1; cvt.u32.u64 %0, t; }"
        : "=r"(a) : "l"(p));
    return a;
}
__device__ __forceinline__ void ldsm4(uint32_t* r, uint32_t addr) {
    asm volatile("ldmatrix.sync.aligned.m8n8.x4.shared.b16 {%0,%1,%2,%3}, [%4];"
                 : "=r"(r[0]), "=r"(r[1]), "=r"(r[2]), "=r"(r[3]) : "r"(addr));
}
__device__ __forceinline__ void mma16816v(float* c, uint4 a,
                                          uint32_t b0, uint32_t b1) {
    asm volatile("mma.sync.aligned.m16n8k16.row.col.f32.bf16.bf16.f32 "
                 "{%0,%1,%2,%3}, {%4,%5,%6,%7}, {%8,%9}, {%0,%1,%2,%3};"
                 : "+f"(c[0]), "+f"(c[1]), "+f"(c[2]), "+f"(c[3])
                 : "r"(a.x), "r"(a.y), "r"(a.z), "r"(a.w), "r"(b0), "r"(b1));
}
__device__ __forceinline__ uint32_t pack_hi_lo(float v0, float v1, uint32_t& lo) {
    __nv_bfloat16 h0 = __float2bfloat16(v0);
    __nv_bfloat16 h1 = __float2bfloat16(v1);
    __nv_bfloat16 l0 = __float2bfloat16(v0 - __bfloat162float(h0));
    __nv_bfloat16 l1 = __float2bfloat16(v1 - __bfloat162float(h1));
    lo = ((uint32_t)__bfloat16_as_ushort(l1) << 16) | __bfloat16_as_ushort(l0);
    return ((uint32_t)__bfloat16_as_ushort(h1) << 16) | __bfloat16_as_ushort(h0);
}
// ---- packed f32x2 helpers ----
__device__ __forceinline__ uint64_t pk2(float lo, float hi) {
    uint64_t r; asm("mov.b64 %0, {%1, %2};" : "=l"(r) : "f"(lo), "f"(hi)); return r;
}
__device__ __forceinline__ void upk2(float& lo, float& hi, uint64_t v) {
    asm("mov.b64 {%0, %1}, %2;" : "=f"(lo), "=f"(hi) : "l"(v));
}
__device__ __forceinline__ void fma2(uint64_t& d, uint64_t a, uint64_t b) {
    asm("fma.rn.f32x2 %0, %1, %2, %0;" : "+l"(d) : "l"(a), "l"(b));
}
__device__ __forceinline__ uint64_t mul2(uint64_t a, uint64_t b) {
    uint64_t d; asm("mul.rn.f32x2 %0, %1, %2;" : "=l"(d) : "l"(a), "l"(b));
    return d;
}

// circ conv body, i-parity P compile-time (see R9).
template<int P>
__device__ __forceinline__ void circ_par(const float* qb, const float* kb,
                                         int A0, float* outv)
{
    uint64_t krp[4][8];
    #pragma unroll
    for (int t = 0; t < 4; ++t) {
        #pragma unroll
        for (int c = 0; c < 8; ++c) {
            int r0 = (2*t + P + A0) & 7;
            int r1 = (2*t + P + 1 + A0) & 7;
            krp[t][c] = pk2(kb[r0*8 + c], kb[r1*8 + c]);
        }
    }
    uint64_t acc2[2][8];
    #pragma unroll
    for (int rp = 0; rp < 2; ++rp)
        #pragma unroll
        for (int bb = 0; bb < 8; ++bb) acc2[rp][bb] = pk2(0.f, 0.f);
    #pragma unroll
    for (int ii = 0; ii < 4; ++ii) {
        const int i = P + 2*ii;
        #pragma unroll
        for (int j = 0; j < 8; ++j) {
            float qs = qb[i*8 + j];
            uint64_t qq = pk2(qs, qs);
            #pragma unroll
            for (int rp = 0; rp < 2; ++rp) {
                const int t = (rp - P - ii) & 3;
                #pragma unroll
                for (int bb = 0; bb < 8; ++bb)
                    fma2(acc2[rp][bb], qq, krp[t][(bb - j) & 7]);
            }
        }
    }
    #pragma unroll
    for (int rp = 0; rp < 2; ++rp)
        #pragma unroll
        for (int bb = 0; bb < 8; ++bb)
            upk2(outv[(2*rp)*8 + bb], outv[(2*rp+1)*8 + bb], acc2[rp][bb]);
}

// ---- prep kernel: pack weights into mma A-fragment layout ----
__global__ void prep_weights(const float* __restrict__ w_hidden,
                             const float* __restrict__ w_proj)
{
    int t = blockIdx.x * blockDim.x + threadIdx.x;
    if (t < 3072) {
        int c = t >> 10, s = t & 1023;
        int lane = s & 31, ks = (s >> 5) & 3, mt = (s >> 7) & 1, mg = s >> 8;
        #pragma unroll
        for (int r = 0; r < 4; ++r) {
            int row = c * 128 + mg * 32 + mt * 16 + (r & 1) * 8 + (lane >> 2);
            int col = ks * 16 + ((r >> 1) & 1) * 8 + (lane & 3) * 2;
            float v0 = w_hidden[row * 64 + col];
            float v1 = w_hidden[row * 64 + col + 1];
            uint32_t lp, hp = pack_hi_lo(v0, v1, lp);
            g_wfh[c][s * 4 + r] = hp;
            g_wfl[c][s * 4 + r] = lp;
        }
    } else if (t < 4096) {
        int s = t - 3072;
        int lane = s & 31, ks = (s >> 5) & 7, mg = s >> 8;
        #pragma unroll
        for (int r = 0; r < 4; ++r) {
            int row = mg * 16 + (r & 1) * 8 + (lane >> 2);
            int col = ks * 16 + ((r >> 1) & 1) * 8 + (lane & 3) * 2;
            float v0 = w_proj[row * 128 + col];
            float v1 = w_proj[row * 128 + col + 1];
            uint32_t lp, hp = pack_hi_lo(v0, v1, lp);
            g_pfh[s * 4 + r] = hp;
            g_pfl[s * 4 + r] = lp;
        }
    }
}

__global__ __launch_bounds__(512, 1)
void fsas_fused_kernel(const float* __restrict__ x,
                       const float* __restrict__ w_dw,
                       const float* __restrict__ g_norm,
                       const float* __restrict__ g_qnorm,
                       const float* __restrict__ g_knorm,
                       float* __restrict__ out)
{
    extern __shared__ float sm[];
    const int tid  = threadIdx.x;
    const int lane = tid & 31;
    const int warp = tid >> 5;
    const int px = blockIdx.x, py = blockIdx.y, b = blockIdx.z;
    const int gx0 = px * 8, gy0 = py * 8;

    char* smc = (char*)sm;
    const uint32_t sbase = smem_u32(sm);
    const uint32_t arena = sbase + ARENA_F * 4;
    const int mg = warp & 3;

    // ---- prefetch: A-frags chunk 0 + dw chunk 0 ----
    uint4 afh[2][4], afl[2][4];
    #pragma unroll
    for (int mt = 0; mt < 2; ++mt)
        #pragma unroll
        for (int ks = 0; ks < 4; ++ks) {
            int slot = ((mg * 2 + mt) * 4 + ks) * 32 + lane;
            afh[mt][ks] = *(const uint4*)&g_wfh[0][slot * 4];
            afl[mt][ks] = *(const uint4*)&g_wfl[0][slot * 4];
        }
    float dwpre[3];
    #pragma unroll
    for (int t = 0; t < 3; ++t) {
        int idx = tid + t * 512;
        dwpre[t] = (idx < 1152) ? __ldg(w_dw + idx) : 0.f;
    }

    // ---- phase 0: x halo (coalesced) -> bf16 hi/lo Xt tiles; sincos; g ----
    const float* xb = x + (size_t)b * 64 * HH * WW;
    for (int it = warp; it < 104; it += 16) {
        int cpBase = it / 13;
        int posBase = it - cpBase * 13;
        int cp  = cpBase * 4 + (lane >> 3);
        int pos = posBase * 8 + (lane & 7);
        float x0 = 0.f, x1 = 0.f;
        if (pos < 100) {
            int Y = pos / 10, X = pos - Y * 10;
            int gy = gy0 - 1 + Y, gx = gx0 - 1 + X;
            if ((unsigned)gy < HH && (unsigned)gx < WW) {
                size_t base = (size_t)(2 * cp) * (HH * WW) + gy * WW + gx;
                x0 = __ldg(xb + base);
                x1 = __ldg(xb + base + (size_t)(HH * WW));
            }
        }
        uint32_t lp, hp = pack_hi_lo(x0, x1, lp);
        uint32_t off = (uint32_t)(pos * 144 + cp * 4);
        *(uint32_t*)(smc + ARENA_F * 4 + XHI + off) = hp;
        *(uint32_t*)(smc + ARENA_F * 4 + XLO + off) = lp;
    }
    {   // sincos table
        int flag = tid >> 8, mm = (tid >> 3) & 31, d = tid & 7;
        float pos = (float)((flag ? gx0 : gy0) + d);
        float inv = exp2f(-L2T_OVER_32 * (float)mm);
        float sn, cs;
        sincosf(pos * inv, &sn, &cs);
        sm[OFF_SC + flag * 256 + mm * 8 + d]       = cs;
        sm[OFF_SC + 512 + flag * 256 + mm * 8 + d] = sn;
    }
    if (tid < 384) {
        float v = (tid < 128) ? __ldg(g_norm + tid)
                : (tid < 256) ? __ldg(g_qnorm + tid - 128)
                              : __ldg(g_knorm + tid - 256);
        sm[OFF_G + tid] = v;
    }
    {
        float* dwb0 = (float*)(smc + ARENA_F * 4 + DWB);
        #pragma unroll
        for (int t = 0; t < 3; ++t) {
            int idx = tid + t * 512;
            if (idx < 1152) dwb0[idx] = dwpre[t];
        }
    }
    #pragma unroll
    for (int t = 0; t < 3; ++t) {
        int idx = tid + t * 512;
        dwpre[t] = (idx < 1152) ? __ldg(w_dw + 1152 + idx) : 0.f;
    }
    __syncthreads();

    // ============ phase 1: expand (HMMA, A from regs) + depthwise ============
    for (int c = 0; c < 3; ++c) {
        {
            const int ng = warp >> 2;
            const int nt0 = (ng == 0) ? 0 : 3 * ng + 1;
            const int cnt = (ng == 0) ? 4 : 3;
            for (int t = 0; t < cnt; ++t) {
                int nt = nt0 + t;
                float acc[2][4] = {};
                const uint32_t bB = arena + XHI + (lane >> 4) * (XLO - XHI)
                                    + (nt * 8 + (lane & 7)) * 144
                                    + ((lane >> 3) & 1) * 16;
                #pragma unroll
                for (int ks = 0; ks < 4; ++ks) {
                    uint32_t bf[4];
                    ldsm4(bf, bB + ks * 32);
                    #pragma unroll
                    for (int mt = 0; mt < 2; ++mt) {
                        mma16816v(acc[mt], afh[mt][ks], bf[0], bf[1]);
                        mma16816v(acc[mt], afh[mt][ks], bf[2], bf[3]);
                        mma16816v(acc[mt], afl[mt][ks], bf[0], bf[1]);
                    }
                }
                int p = nt * 8 + 2 * (lane & 3);
                #pragma unroll
                for (int mt = 0; mt < 2; ++mt) {
                    int o = mg * 32 + mt * 16 + (lane >> 2);
                    if (p < 100) {
                        sm[OFF_HID + o * 101 + p]       = acc[mt][0];
                        sm[OFF_HID + (o + 8) * 101 + p] = acc[mt][2];
                    }
                    if (p + 1 < 100) {
                        sm[OFF_HID + o * 101 + p + 1]       = acc[mt][1];
                        sm[OFF_HID + (o + 8) * 101 + p + 1] = acc[mt][3];
                    }
                }
            }
        }
        __syncthreads();

        if (c < 2) {
            #pragma unroll
            for (int mt = 0; mt < 2; ++mt)
                #pragma unroll
                for (int ks = 0; ks < 4; ++ks) {
                    int slot = ((mg * 2 + mt) * 4 + ks) * 32 + lane;
                    afh[mt][ks] = *(const uint4*)&g_wfh[c + 1][slot * 4];
                    afl[mt][ks] = *(const uint4*)&g_wfl[c + 1][slot * 4];
                }
            float* dwbn = (float*)(smc + ARENA_F * 4 + DWB + ((c + 1) & 1) * 4608);
            #pragma unroll
            for (int t = 0; t < 3; ++t) {
                int idx = tid + t * 512;
                if (idx < 1152) dwbn[idx] = dwpre[t];
            }
            if (c < 1) {
                #pragma unroll
                for (int t = 0; t < 3; ++t) {
                    int idx = tid + t * 512;
                    dwpre[t] = (idx < 1152) ? __ldg(w_dw + 2 * 1152 + idx) : 0.f;
                }
            }
        }

        // depthwise 3x3 (f32x2)
        {
            int ch = tid & 127, g = tid >> 7;
            const float* wd = (const float*)(smc + ARENA_F * 4 + DWB
                                             + (c & 1) * 4608) + ch * 9;
            uint64_t ww[9];
            #pragma unroll
            for (int t = 0; t < 9; ++t) { float w = wd[t]; ww[t] = pk2(w, w); }
            const float* hb = &sm[OFF_HID + ch * 101 + 2 * g];
            uint64_t Ap[3], Bp[3], Cp[3];
            {
                float a0 = hb[0], a1 = hb[1], a2 = hb[2], a3 = hb[3];
                Ap[0] = pk2(a0, a1); Ap[1] = pk2(a1, a2); Ap[2] = pk2(a2, a3);
                float b0 = hb[10], b1 = hb[11], b2 = hb[12], b3 = hb[13];
                Bp[0] = pk2(b0, b1); Bp[1] = pk2(b1, b2); Bp[2] = pk2(b2, b3);
            }
            float* qrow = &sm[OFF_QKV + (c * 128 + ch) * 65 + 2 * g];
            #pragma unroll
            for (int r = 2; r < 10; ++r) {
                float c0 = hb[r*10+0], c1 = hb[r*10+1], c2 = hb[r*10+2], c3 = hb[r*10+3];
                Cp[0] = pk2(c0, c1); Cp[1] = pk2(c1, c2); Cp[2] = pk2(c2, c3);
                uint64_t s2 = pk2(0.f, 0.f);
                fma2(s2, ww[0], Ap[0]); fma2(s2, ww[1], Ap[1]); fma2(s2, ww[2], Ap[2]);
                fma2(s2, ww[3], Bp[0]); fma2(s2, ww[4], Bp[1]); fma2(s2, ww[5], Bp[2]);
                fma2(s2, ww[6], Cp[0]); fma2(s2, ww[7], Cp[1]); fma2(s2, ww[8], Cp[2]);
                float o0, o1; upk2(o0, o1, s2);
                int yy = r - 2;
                qrow[yy * 8 + 0] = o0; qrow[yy * 8 + 1] = o1;
                Ap[0]=Bp[0]; Ap[1]=Bp[1]; Ap[2]=Bp[2];
                Bp[0]=Cp[0]; Bp[1]=Cp[1]; Bp[2]=Cp[2];
            }
        }
        if (c < 2) __syncthreads();
    }

    // ---- phase 2: RMS factors for q and k (warp -> 4 pixels) ----
    #pragma unroll
    for (int pi = 0; pi < 4; ++pi) {
        int pix = warp * 4 + pi;
        float sq = 0.f, sk = 0.f;
        #pragma unroll
        for (int r = 0; r < 4; ++r) {
            int cc = lane + r * 32;
            float qv = sm[OFF_QKV + cc * 65 + pix];
            float kv = sm[OFF_QKV + (128 + cc) * 65 + pix];
            sq = fmaf(qv, qv, sq);
            sk = fmaf(kv, kv, sk);
        }
        #pragma unroll
        for (int off = 16; off; off >>= 1) {
            sq += __shfl_xor_sync(0xffffffffu, sq, off);
            sk += __shfl_xor_sync(0xffffffffu, sk, off);
        }
        if (lane == 0) {
            sm[OFF_RQ + pix] = rsqrtf(sq * (1.f / 128.f) + EPSF);
            sm[OFF_RK + pix] = rsqrtf(sk * (1.f / 128.f) + EPSF);
        }
    }
    __syncthreads();

    // ---- phase 3: RMSNorm + 2D RoPE, f32x2 over pixel pairs (4 iters) ----
    for (int idx = tid; idx < 64 * 32; idx += 512) {
        int m = idx >> 5, pp = idx & 31;
        int pix = 2 * pp;
        int flag = m >> 5, mm = m & 31;
        uint64_t cs2, sn2;
        if (flag == 0) {
            float cs = sm[OFF_SC + mm * 8 + (pix >> 3)];
            float sn = sm[OFF_SC + 512 + mm * 8 + (pix >> 3)];
            cs2 = pk2(cs, cs); sn2 = pk2(sn, sn);
        } else {
            int d = pix & 7;   // even
            cs2 = *(const uint64_t*)&sm[OFF_SC + 256 + mm * 8 + d];
            sn2 = *(const uint64_t*)&sm[OFF_SC + 512 + 256 + mm * 8 + d];
        }
        uint64_t nsn2 = sn2 ^ 0x8000000080000000ULL;
        int c0 = 2 * m;
        uint64_t rq2 = *(const uint64_t*)&sm[OFF_RQ + pix];
        uint64_t rk2 = *(const uint64_t*)&sm[OFF_RK + pix];
        float gq0 = sm[OFF_G + 128 + c0], gq1 = sm[OFF_G + 129 + c0];
        float gk0 = sm[OFF_G + 256 + c0], gk1 = sm[OFF_G + 257 + c0];

        float* q0p = &sm[OFF_QKV + c0 * 65 + pix];          // even row: 8B aligned
        float* q1p = &sm[OFF_QKV + (c0 + 1) * 65 + pix];    // odd row: 4B only
        uint64_t q0 = *(const uint64_t*)q0p;
        uint64_t q1 = pk2(q1p[0], q1p[1]);
        uint64_t q0s = mul2(mul2(q0, rq2), pk2(gq0, gq0));
        uint64_t q1s = mul2(mul2(q1, rq2), pk2(gq1, gq1));
        uint64_t o0 = mul2(q0s, cs2); fma2(o0, q1s, nsn2);
        uint64_t o1 = mul2(q1s, cs2); fma2(o1, q0s, sn2);
        *(uint64_t*)q0p = o0;
        { float a, bq; upk2(a, bq, o1); q1p[0] = a; q1p[1] = bq; }

        float* k0p = &sm[OFF_QKV + (128 + c0) * 65 + pix];  // even row
        float* k1p = &sm[OFF_QKV + (129 + c0) * 65 + pix];  // odd row
        uint64_t k0 = *(const uint64_t*)k0p;
        uint64_t k1 = pk2(k1p[0], k1p[1]);
        uint64_t k0s = mul2(mul2(k0, rk2), pk2(gk0, gk0));
        uint64_t k1s = mul2(mul2(k1, rk2), pk2(gk1, gk1));
        uint64_t p0 = mul2(k0s, cs2); fma2(p0, k1s, nsn2);
        uint64_t p1 = mul2(k1s, cs2); fma2(p1, k0s, sn2);
        *(uint64_t*)k0p = p0;
        { float a, bk; upk2(a, bk, p1); k1p[0] = a; k1p[1] = bk; }
    }
    __syncthreads();

    // ---- phase 4: circ conv, f32x2 parity-split ----
    {
        const int cc = tid & 127;
        const int A0 = ((tid >> 7) & 1) * 4;
        const int P  = tid >> 8;
        const float* qb = &sm[OFF_QKV + cc * 65];
        const float* kb = &sm[OFF_QKV + (128 + cc) * 65];
        float v32[32];
        if (P == 0) circ_par<0>(qb, kb, A0, v32);
        else        circ_par<1>(qb, kb, A0, v32);

        float* scratch = (float*)(smc + ARENA_F * 4 + CBH);
        int s = tid & 255;
        if (P == 1) {
            #pragma unroll
            for (int t = 0; t < 32; ++t) scratch[s * 33 + t] = v32[t];
        }
        __syncthreads();
        if (P == 0) {
            #pragma unroll
            for (int t = 0; t < 32; ++t) {
                float tot = v32[t] + scratch[s * 33 + t];
                sm[OFF_CORR + cc * 65 + (A0 + (t >> 3)) * 8 + (t & 7)] = tot;
            }
        }
    }
    __syncthreads();

    // ---- proj A-frags via LDG (latency hidden under phases 5+6) ----
    uint4 pfh[8], pfl[8];
    #pragma unroll
    for (int ks = 0; ks < 8; ++ks) {
        int slot = (mg * 8 + ks) * 32 + lane;
        pfh[ks] = *(const uint4*)&g_pfh[slot * 4];
        pfl[ks] = *(const uint4*)&g_pfl[slot * 4];
    }

    // ---- phase 5: corr RMS factor (warp -> 4 pixels) ----
    #pragma unroll
    for (int pi = 0; pi < 4; ++pi) {
        int pix = warp * 4 + pi;
        float sc = 0.f;
        #pragma unroll
        for (int r = 0; r < 4; ++r) {
            float cv = sm[OFF_CORR + (lane + r * 32) * 65 + pix];
            sc = fmaf(cv, cv, sc);
        }
        #pragma unroll
        for (int off = 16; off; off >>= 1)
            sc += __shfl_xor_sync(0xffffffffu, sc, off);
        if (lane == 0)
            sm[OFF_RN + pix] = rsqrtf(sc * (1.f / 128.f) + EPSF);
    }
    __syncthreads();

    // ---- phase 6: (v*g*rn*corr) -> bf16 hi/lo B tiles, kp pairs (4 iters) ----
    for (int idx = tid; idx < 64 * 32; idx += 512) {
        int pix = idx >> 5, kpp = idx & 31;
        int kp0 = 2 * kpp, k0 = 2 * kp0;
        float rnp = sm[OFF_RN + pix];
        uint32_t hp0, lp0, hp1, lp1;
        {
            float cA = sm[OFF_CORR + k0 * 65 + pix];
            float cB = sm[OFF_CORR + (k0 + 1) * 65 + pix];
            float vA = sm[OFF_QKV + (256 + k0) * 65 + pix];
            float vB = sm[OFF_QKV + (257 + k0) * 65 + pix];
            float w0 = vA * cA * rnp * sm[OFF_G + k0];
            float w1 = vB * cB * rnp * sm[OFF_G + k0 + 1];
            hp0 = pack_hi_lo(w0, w1, lp0);
        }
        {
            float cA = sm[OFF_CORR + (k0 + 2) * 65 + pix];
            float cB = sm[OFF_CORR + (k0 + 3) * 65 + pix];
            float vA = sm[OFF_QKV + (258 + k0) * 65 + pix];
            float vB = sm[OFF_QKV + (259 + k0) * 65 + pix];
            float w2 = vA * cA * rnp * sm[OFF_G + k0 + 2];
            float w3 = vB * cB * rnp * sm[OFF_G + k0 + 3];
            hp1 = pack_hi_lo(w2, w3, lp1);
        }
        uint2 hpv = make_uint2(hp0, hp1), lpv = make_uint2(lp0, lp1);
        *(uint2*)(smc + ARENA_F * 4 + CBH + pix * 272 + kp0 * 4) = hpv;
        *(uint2*)(smc + ARENA_F * 4 + CBL + pix * 272 + kp0 * 4) = lpv;
    }
    __syncthreads();

    // ---- phase 7: projection HMMA on 16 warps (A from regs) ----
    {
        const int nh = warp >> 2;
        float* ob = out + (size_t)b * 64 * HH * WW;
        #pragma unroll
        for (int t = 0; t < 2; ++t) {
            int nt = nh * 2 + t;
            float acc[4] = {};
            const uint32_t bB = arena + CBH + (lane >> 4) * (CBL - CBH)
                                + (nt * 8 + (lane & 7)) * 272
                                + ((lane >> 3) & 1) * 16;
            #pragma unroll
            for (int ks = 0; ks < 8; ++ks) {
                uint32_t bf[4];
                ldsm4(bf, bB + ks * 32);
                mma16816v(acc, pfh[ks], bf[0], bf[1]);
                mma16816v(acc, pfh[ks], bf[2], bf[3]);
                mma16816v(acc, pfl[ks], bf[0], bf[1]);
            }
            int o = mg * 16 + (lane >> 2);
            int gy = gy0 + nt;
            int gxp = gx0 + 2 * (lane & 3);
            *(float2*)(ob + (size_t)o * (HH * WW) + gy * WW + gxp)
                = make_float2(acc[0], acc[1]);
            *(float2*)(ob + (size_t)(o + 8) * (HH * WW) + gy * WW + gxp)
                = make_float2(acc[2], acc[3]);
        }
    }
}

extern "C" void kernel_launch(void* const* d_in, const int* in_sizes, int n_in,
                              void* d_out, int out_size)
{
    (void)in_sizes; (void)n_in; (void)out_size;
    const float* x        = (const float*)d_in[0];
    const float* w_hidden = (const float*)d_in[1];
    const float* w_dw     = (const float*)d_in[2];
    const float* w_proj   = (const float*)d_in[3];
    const float* g_norm   = (const float*)d_in[4];
    const float* g_qnorm  = (const float*)d_in[5];
    const float* g_knorm  = (const float*)d_in[6];
    float* out = (float*)d_out;

    prep_weights<<<16, 256>>>(w_hidden, w_proj);

    cudaFuncSetAttribute(fsas_fused_kernel,
                         cudaFuncAttributeMaxDynamicSharedMemorySize, SMEM_BYTES);
    dim3 grid(WW / 8, HH / 8, 4);
    fsas_fused_kernel<<<grid, 512, SMEM_BYTES>>>(
        x, w_dw, g_norm, g_qnorm, g_knorm, out);
}